// round 7
// baseline (speedup 1.0000x reference)
#include <cuda_runtime.h>
#include <cuda_bf16.h>
#include <cstdint>

#define NNODES 50000
#define NEDGES 600000
#define FDIM   128

// ---------------------------------------------------------------------------
// Device scratch (no allocations allowed)
// ---------------------------------------------------------------------------
__device__ float g_xj[NNODES * FDIM];         // aggregated neighbor features
__device__ int   g_ei_is_i64;                 // edge_index dtype flag
__device__ __nv_bfloat16 g_w2hi[FDIM * FDIM]; // W2^T hi, layout [n][k]
__device__ __nv_bfloat16 g_w2lo[FDIM * FDIM]; // W2^T lo, layout [n][k]

// ---------------------------------------------------------------------------
// Kernel: probe edge_index dtype. Real int64 values are all in [0,N);
// int32 reinterpreted as int64 lands out of range with overwhelming prob.
// ---------------------------------------------------------------------------
__global__ void probe_ei_kernel(const void* ei) {
    if (threadIdx.x == 0 && blockIdx.x == 0) {
        const long long* p = (const long long*)ei;
        int ok = 1;
#pragma unroll
        for (int i = 0; i < 16; i++) {
            long long v = p[i];
            if (v < 0 || v >= NNODES) ok = 0;
        }
        g_ei_is_i64 = ok;
    }
}

// ---------------------------------------------------------------------------
// W2 prep: transpose to [n][k] and split fp32 -> bf16 hi + lo.
// ---------------------------------------------------------------------------
__global__ void w2_prep_kernel(const float* __restrict__ W2) {
    int idx = blockIdx.x * blockDim.x + threadIdx.x;
    if (idx < FDIM * FDIM) {
        int k = idx >> 7, n = idx & 127;
        float f = W2[idx];
        __nv_bfloat16 h = __float2bfloat16(f);
        float l = f - __bfloat162float(h);
        g_w2hi[n * FDIM + k] = h;
        g_w2lo[n * FDIM + k] = __float2bfloat16(l);
    }
}

// ---------------------------------------------------------------------------
// Zero the accumulator (required every launch; graph replays).
// ---------------------------------------------------------------------------
__global__ void zero_xj_kernel() {
    const int total4 = NNODES * FDIM / 4;
    int idx = blockIdx.x * blockDim.x + threadIdx.x;
    if (idx < total4) {
        reinterpret_cast<float4*>(g_xj)[idx] = make_float4(0.f, 0.f, 0.f, 0.f);
    }
}

// ---------------------------------------------------------------------------
// Scatter-add: block stages 64 edges' indices coalesced through smem,
// then each of 8 warps handles 8 edges; lane l moves floats [4l,4l+4)
// via red.global.add.v4.f32 (no return trip).
// ---------------------------------------------------------------------------
__global__ __launch_bounds__(256)
void scatter_kernel(const float* __restrict__ x, const void* __restrict__ edge_index) {
    __shared__ int ss[64];
    __shared__ int sd[64];
    const int tid = threadIdx.x;
    const long long base = (long long)blockIdx.x * 64;

    if (tid < 128) {
        int which = tid >> 6;          // 0 = src, 1 = dst
        int i = tid & 63;
        long long e = base + i;
        int v = 0;
        if (e < NEDGES) {
            long long ofs = (long long)which * NEDGES + e;
            if (g_ei_is_i64) v = (int)((const long long*)edge_index)[ofs];
            else             v = ((const int*)edge_index)[ofs];
        }
        if (which == 0) ss[i] = v; else sd[i] = v;
    }
    __syncthreads();

    const int wid = tid >> 5;
    const int lane = tid & 31;
#pragma unroll
    for (int j = 0; j < 8; j++) {
        int i = wid * 8 + j;
        long long e = base + i;
        if (e >= NEDGES) break;
        int s = ss[i], d = sd[i];
        const float4 v = *reinterpret_cast<const float4*>(&x[(size_t)s * FDIM + lane * 4]);
        float* dst = &g_xj[(size_t)d * FDIM + lane * 4];
        asm volatile("red.global.add.v4.f32 [%0], {%1, %2, %3, %4};"
                     :: "l"(dst), "f"(v.x), "f"(v.y), "f"(v.z), "f"(v.w)
                     : "memory");
    }
}

// ---------------------------------------------------------------------------
// Tensor-core GEMM via mma.sync (bf16x3): C = A @ W2 + bias.
// 256 threads / 8 warps; warp computes 16 rows x 128 cols, K=128.
// A fragments from direct coalesced f32 loads (each element read once).
// B fragments from L1-resident transposed hi/lo tables.
// ---------------------------------------------------------------------------
__device__ __forceinline__ void mma_bf16(float* c, uint32_t a0, uint32_t a1,
                                         uint32_t a2, uint32_t a3,
                                         uint32_t b0, uint32_t b1) {
    asm volatile(
        "mma.sync.aligned.m16n8k16.row.col.f32.bf16.bf16.f32 "
        "{%0,%1,%2,%3}, {%4,%5,%6,%7}, {%8,%9}, {%0,%1,%2,%3};"
        : "+f"(c[0]), "+f"(c[1]), "+f"(c[2]), "+f"(c[3])
        : "r"(a0), "r"(a1), "r"(a2), "r"(a3), "r"(b0), "r"(b1));
}

__device__ __forceinline__ uint32_t pack_hi(float2 f) {
    __nv_bfloat162 h = __floats2bfloat162_rn(f.x, f.y);
    return *reinterpret_cast<uint32_t*>(&h);
}
__device__ __forceinline__ uint32_t pack_lo(float2 f) {
    float lx = f.x - __bfloat162float(__float2bfloat16(f.x));
    float ly = f.y - __bfloat162float(__float2bfloat16(f.y));
    __nv_bfloat162 h = __floats2bfloat162_rn(lx, ly);
    return *reinterpret_cast<uint32_t*>(&h);
}

__global__ __launch_bounds__(256)
void mma_gemm_kernel(const float* __restrict__ A,
                     const float* __restrict__ bias,
                     float* __restrict__ C,
                     int nrows) {
    const int lane = threadIdx.x & 31;
    const int wid  = threadIdx.x >> 5;
    const int g = lane >> 2;      // 0..7
    const int t = lane & 3;       // 0..3
    const int row0 = blockIdx.x * 128 + wid * 16;
    const int r0 = row0 + g;
    const int r1 = row0 + g + 8;

    float acc[16][4];
#pragma unroll
    for (int nt = 0; nt < 16; nt++)
#pragma unroll
        for (int j = 0; j < 4; j++) acc[nt][j] = 0.f;

    const float2 z2 = make_float2(0.f, 0.f);

#pragma unroll 1
    for (int kt = 0; kt < 8; kt++) {
        const int k0 = kt * 16;
        float2 f0 = z2, f1 = z2, f2 = z2, f3 = z2;
        if (r0 < nrows) {
            f0 = *reinterpret_cast<const float2*>(&A[(size_t)r0 * FDIM + k0 + 2 * t]);
            f2 = *reinterpret_cast<const float2*>(&A[(size_t)r0 * FDIM + k0 + 2 * t + 8]);
        }
        if (r1 < nrows) {
            f1 = *reinterpret_cast<const float2*>(&A[(size_t)r1 * FDIM + k0 + 2 * t]);
            f3 = *reinterpret_cast<const float2*>(&A[(size_t)r1 * FDIM + k0 + 2 * t + 8]);
        }
        uint32_t ah0 = pack_hi(f0), ah1 = pack_hi(f1), ah2 = pack_hi(f2), ah3 = pack_hi(f3);
        uint32_t al0 = pack_lo(f0), al1 = pack_lo(f1), al2 = pack_lo(f2), al3 = pack_lo(f3);

#pragma unroll
        for (int nt = 0; nt < 16; nt++) {
            const int nrow = nt * 8 + g;
            const int kcol = k0 + 2 * t;
            uint32_t bh0 = *reinterpret_cast<const uint32_t*>(&g_w2hi[nrow * FDIM + kcol]);
            uint32_t bh1 = *reinterpret_cast<const uint32_t*>(&g_w2hi[nrow * FDIM + kcol + 8]);
            uint32_t bl0 = *reinterpret_cast<const uint32_t*>(&g_w2lo[nrow * FDIM + kcol]);
            uint32_t bl1 = *reinterpret_cast<const uint32_t*>(&g_w2lo[nrow * FDIM + kcol + 8]);
            mma_bf16(acc[nt], ah0, ah1, ah2, ah3, bh0, bh1);
            mma_bf16(acc[nt], ah0, ah1, ah2, ah3, bl0, bl1);
            mma_bf16(acc[nt], al0, al1, al2, al3, bh0, bh1);
        }
    }

#pragma unroll
    for (int nt = 0; nt < 16; nt++) {
        const int c = nt * 8 + 2 * t;
        float bx = __ldg(&bias[c]);
        float by = __ldg(&bias[c + 1]);
        if (r0 < nrows) {
            float2 o = make_float2(acc[nt][0] + bx, acc[nt][1] + by);
            *reinterpret_cast<float2*>(&C[(size_t)r0 * FDIM + c]) = o;
        }
        if (r1 < nrows) {
            float2 o = make_float2(acc[nt][2] + bx, acc[nt][3] + by);
            *reinterpret_cast<float2*>(&C[(size_t)r1 * FDIM + c]) = o;
        }
    }
}

// ---------------------------------------------------------------------------
// kernel_launch
// Inputs: 0:x, 1:edge_index, 2:edge_weight(u), 3:W1(u), 4:b1(u),
//         5:W2, 6:b2, 7:a(u), 8:b(u).  Output: [N,128] f32
// ---------------------------------------------------------------------------
extern "C" void kernel_launch(void* const* d_in, const int* in_sizes, int n_in,
                              void* d_out, int out_size) {
    const float* x   = (const float*)d_in[0];
    const void*  ei  = d_in[1];
    const float* W2  = (const float*)d_in[5];
    const float* b2  = (const float*)d_in[6];
    float*       out = (float*)d_out;

    float* xj = nullptr;
    cudaGetSymbolAddress((void**)&xj, g_xj);

    probe_ei_kernel<<<1, 32>>>(ei);
    w2_prep_kernel<<<(FDIM * FDIM + 255) / 256, 256>>>(W2);
    {
        int total4 = NNODES * FDIM / 4;
        zero_xj_kernel<<<(total4 + 255) / 256, 256>>>();
    }
    scatter_kernel<<<(NEDGES + 63) / 64, 256>>>(x, ei);
    mma_gemm_kernel<<<(NNODES + 127) / 128, 256>>>(xj, b2, out, NNODES);
}

// round 8
// speedup vs baseline: 1.4333x; 1.4333x over previous
#include <cuda_runtime.h>
#include <cuda_bf16.h>
#include <cstdint>

#define NNODES 50000
#define NEDGES 600000
#define FDIM   128
#define ZERO_BLOCKS 6250   // 6250*256 float4 = exactly NNODES*FDIM/4

// ---------------------------------------------------------------------------
// Device scratch (no allocations allowed)
// ---------------------------------------------------------------------------
__device__ float g_xj[NNODES * FDIM];   // aggregated neighbor features
__device__ int   g_ei_is_i64;           // edge_index dtype flag
// Prepacked per-thread B fragments for m16n8k16 bf16 MMA.
// Layout: [kt (8)][nt (16)][lane (32)] of uint4 {bh0, bh1, bl0, bl1}. 64KB.
__device__ uint4 g_w2frag[8 * 16 * 32];

__device__ __forceinline__ uint32_t pack2_hi(float a, float b) {
    __nv_bfloat162 h = __floats2bfloat162_rn(a, b);
    return *reinterpret_cast<uint32_t*>(&h);
}
__device__ __forceinline__ uint32_t pack2_lo(float a, float b) {
    float la = a - __bfloat162float(__float2bfloat16(a));
    float lb = b - __bfloat162float(__float2bfloat16(b));
    __nv_bfloat162 h = __floats2bfloat162_rn(la, lb);
    return *reinterpret_cast<uint32_t*>(&h);
}

// ---------------------------------------------------------------------------
// Fused prep: [0, ZERO_BLOCKS) zero g_xj; block ZERO_BLOCKS probes the
// edge_index dtype; remaining 16 blocks pack W2 into MMA fragments.
// ---------------------------------------------------------------------------
__global__ __launch_bounds__(256)
void prep_kernel(const void* __restrict__ ei, const float* __restrict__ W2) {
    int b = blockIdx.x;
    if (b < ZERO_BLOCKS) {
        int idx = b * 256 + threadIdx.x;
        reinterpret_cast<float4*>(g_xj)[idx] = make_float4(0.f, 0.f, 0.f, 0.f);
    } else if (b == ZERO_BLOCKS) {
        if (threadIdx.x == 0) {
            const long long* p = (const long long*)ei;
            int ok = 1;
#pragma unroll
            for (int i = 0; i < 16; i++) {
                long long v = p[i];
                if (v < 0 || v >= NNODES) ok = 0;
            }
            g_ei_is_i64 = ok;
        }
    } else {
        int idx = (b - ZERO_BLOCKS - 1) * 256 + threadIdx.x;  // 0..4095
        if (idx < 8 * 16 * 32) {
            int kt = idx >> 9;
            int nt = (idx >> 5) & 15;
            int lane = idx & 31;
            int g = lane >> 2, t = lane & 3;
            int n = nt * 8 + g;
            int kc = kt * 16 + 2 * t;
            // B^T[n][k] = W2[k][n]; b0 covers k = kc,kc+1; b1 covers k = kc+8,kc+9
            float w00 = W2[kc * FDIM + n];
            float w01 = W2[(kc + 1) * FDIM + n];
            float w10 = W2[(kc + 8) * FDIM + n];
            float w11 = W2[(kc + 9) * FDIM + n];
            uint4 f;
            f.x = pack2_hi(w00, w01);
            f.y = pack2_hi(w10, w11);
            f.z = pack2_lo(w00, w01);
            f.w = pack2_lo(w10, w11);
            g_w2frag[idx] = f;
        }
    }
}

// ---------------------------------------------------------------------------
// Scatter-add: block stages 64 edges' indices coalesced through smem,
// then each of 8 warps handles 8 edges; lane l moves floats [4l,4l+4)
// via red.global.add.v4.f32 (no return trip). LTS-roofline-bound (~57us).
// ---------------------------------------------------------------------------
__global__ __launch_bounds__(256)
void scatter_kernel(const float* __restrict__ x, const void* __restrict__ edge_index) {
    __shared__ int ss[64];
    __shared__ int sd[64];
    const int tid = threadIdx.x;
    const long long base = (long long)blockIdx.x * 64;

    if (tid < 128) {
        int which = tid >> 6;          // 0 = src, 1 = dst
        int i = tid & 63;
        long long e = base + i;
        int v = 0;
        if (e < NEDGES) {
            long long ofs = (long long)which * NEDGES + e;
            if (g_ei_is_i64) v = (int)((const long long*)edge_index)[ofs];
            else             v = ((const int*)edge_index)[ofs];
        }
        if (which == 0) ss[i] = v; else sd[i] = v;
    }
    __syncthreads();

    const int wid = tid >> 5;
    const int lane = tid & 31;
#pragma unroll
    for (int j = 0; j < 8; j++) {
        int i = wid * 8 + j;
        long long e = base + i;
        if (e >= NEDGES) break;
        int s = ss[i], d = sd[i];
        const float4 v = *reinterpret_cast<const float4*>(&x[(size_t)s * FDIM + lane * 4]);
        float* dst = &g_xj[(size_t)d * FDIM + lane * 4];
        asm volatile("red.global.add.v4.f32 [%0], {%1, %2, %3, %4};"
                     :: "l"(dst), "f"(v.x), "f"(v.y), "f"(v.z), "f"(v.w)
                     : "memory");
    }
}

// ---------------------------------------------------------------------------
// Tensor-core GEMM via mma.sync (bf16x3): C = A @ W2 + bias.
// 256 threads / 8 warps; warp computes 16 rows x 128 cols, K=128.
// A fragments from direct coalesced f32 loads; B fragments from the
// prepacked 64KB table -> ONE LDG.128 per 3 MMAs, L1-resident.
// ---------------------------------------------------------------------------
__device__ __forceinline__ void mma_bf16(float* c, uint32_t a0, uint32_t a1,
                                         uint32_t a2, uint32_t a3,
                                         uint32_t b0, uint32_t b1) {
    asm volatile(
        "mma.sync.aligned.m16n8k16.row.col.f32.bf16.bf16.f32 "
        "{%0,%1,%2,%3}, {%4,%5,%6,%7}, {%8,%9}, {%0,%1,%2,%3};"
        : "+f"(c[0]), "+f"(c[1]), "+f"(c[2]), "+f"(c[3])
        : "r"(a0), "r"(a1), "r"(a2), "r"(a3), "r"(b0), "r"(b1));
}

__device__ __forceinline__ uint32_t pack_hi(float2 f) { return pack2_hi(f.x, f.y); }
__device__ __forceinline__ uint32_t pack_lo(float2 f) { return pack2_lo(f.x, f.y); }

__global__ __launch_bounds__(256)
void mma_gemm_kernel(const float* __restrict__ A,
                     const float* __restrict__ bias,
                     float* __restrict__ C,
                     int nrows) {
    const int lane = threadIdx.x & 31;
    const int wid  = threadIdx.x >> 5;
    const int g = lane >> 2;      // 0..7
    const int t = lane & 3;       // 0..3
    const int row0 = blockIdx.x * 128 + wid * 16;
    const int r0 = row0 + g;
    const int r1 = row0 + g + 8;

    float acc[16][4];
#pragma unroll
    for (int nt = 0; nt < 16; nt++)
#pragma unroll
        for (int j = 0; j < 4; j++) acc[nt][j] = 0.f;

    const float2 z2 = make_float2(0.f, 0.f);

#pragma unroll 1
    for (int kt = 0; kt < 8; kt++) {
        const int k0 = kt * 16;
        float2 f0 = z2, f1 = z2, f2 = z2, f3 = z2;
        if (r0 < nrows) {
            f0 = *reinterpret_cast<const float2*>(&A[(size_t)r0 * FDIM + k0 + 2 * t]);
            f2 = *reinterpret_cast<const float2*>(&A[(size_t)r0 * FDIM + k0 + 2 * t + 8]);
        }
        if (r1 < nrows) {
            f1 = *reinterpret_cast<const float2*>(&A[(size_t)r1 * FDIM + k0 + 2 * t]);
            f3 = *reinterpret_cast<const float2*>(&A[(size_t)r1 * FDIM + k0 + 2 * t + 8]);
        }
        uint32_t ah0 = pack_hi(f0), ah1 = pack_hi(f1), ah2 = pack_hi(f2), ah3 = pack_hi(f3);
        uint32_t al0 = pack_lo(f0), al1 = pack_lo(f1), al2 = pack_lo(f2), al3 = pack_lo(f3);

        const uint4* bp = &g_w2frag[(kt * 16) * 32 + lane];
#pragma unroll
        for (int nt = 0; nt < 16; nt++) {
            uint4 bfrag = bp[nt * 32];   // one LDG.128, coalesced 512B/warp
            mma_bf16(acc[nt], ah0, ah1, ah2, ah3, bfrag.x, bfrag.y);
            mma_bf16(acc[nt], ah0, ah1, ah2, ah3, bfrag.z, bfrag.w);
            mma_bf16(acc[nt], al0, al1, al2, al3, bfrag.x, bfrag.y);
        }
    }

#pragma unroll
    for (int nt = 0; nt < 16; nt++) {
        const int c = nt * 8 + 2 * t;
        float bx = __ldg(&bias[c]);
        float by = __ldg(&bias[c + 1]);
        if (r0 < nrows) {
            float2 o = make_float2(acc[nt][0] + bx, acc[nt][1] + by);
            *reinterpret_cast<float2*>(&C[(size_t)r0 * FDIM + c]) = o;
        }
        if (r1 < nrows) {
            float2 o = make_float2(acc[nt][2] + bx, acc[nt][3] + by);
            *reinterpret_cast<float2*>(&C[(size_t)r1 * FDIM + c]) = o;
        }
    }
}

// ---------------------------------------------------------------------------
// kernel_launch
// Inputs: 0:x, 1:edge_index, 2:edge_weight(u), 3:W1(u), 4:b1(u),
//         5:W2, 6:b2, 7:a(u), 8:b(u).  Output: [N,128] f32
// ---------------------------------------------------------------------------
extern "C" void kernel_launch(void* const* d_in, const int* in_sizes, int n_in,
                              void* d_out, int out_size) {
    const float* x   = (const float*)d_in[0];
    const void*  ei  = d_in[1];
    const float* W2  = (const float*)d_in[5];
    const float* b2  = (const float*)d_in[6];
    float*       out = (float*)d_out;

    float* xj = nullptr;
    cudaGetSymbolAddress((void**)&xj, g_xj);

    prep_kernel<<<ZERO_BLOCKS + 1 + 16, 256>>>(ei, W2);
    scatter_kernel<<<(NEDGES + 63) / 64, 256>>>(x, ei);
    mma_gemm_kernel<<<(NNODES + 127) / 128, 256>>>(xj, b2, out, NNODES);
}